// round 12
// baseline (speedup 1.0000x reference)
#include <cuda_runtime.h>
#include <cuda_fp16.h>
#include <mma.h>

using namespace nvcuda;

#define NN 50000
#define NE 1600000
#define HD 128          // HEADS*OUT_DIM
#define NB 196          // ceil(NN/256)

// ---------------- scratch (static device globals; no allocs) ----------------
__device__ uint4  g_h16[(size_t)NN * 16];   // 12.8 MB  h in fp16, 128 halves/row
__device__ float4 g_asrc[NN];
__device__ float4 g_adst[NN];
__device__ int    g_deg[NN];
__device__ int    g_off[NN + 1];
__device__ int    g_boff[NB];
__device__ int    g_bsum[NB];
__device__ int    g_cur[NN];
__device__ int    g_csr_src[NE];
__device__ float4 g_csr_w[NE];

// bit-reinterpret __half2 -> uint32 (no intrinsic exists for this cast)
static __device__ __forceinline__ unsigned int h2u(__half2 h) {
    return *reinterpret_cast<unsigned int*>(&h);
}

// ---------------- K0: zero degree histogram ----------------
__global__ void k_zero() {
    int i = blockIdx.x * blockDim.x + threadIdx.x;
    if (i < NN) g_deg[i] = 0;
}

// ---------------- K1: degree histogram (dst only) ----------------
__global__ void k_deg(const int* __restrict__ ei) {
    int e = blockIdx.x * blockDim.x + threadIdx.x;
    if (e < NE) atomicAdd(&g_deg[ei[NE + e]], 1);
}

// ---------------- K2: tf32 wmma GEMM h = x @ W_lin^T + fused epilogues ------
// Block tile 64(m) x 128(n), K=128 in 4 chunks of 32. 8 warps: warp_m=wid&3,
// warp_n=wid>>2; each warp computes 16x64 via 4 m16n16k8 C fragments.
// A (x) row-major and B (W, since B=W^T K-major) col_major both load as
// straight copies of the row-major globals. C staged to smem (overlaid on the
// dead A/B tiles) for the a_src/a_dst dot and fp16-h pack epilogues.
#define SX_OFF 0            // sx: [64][36] floats  = 2304
#define SW_OFF 2304         // sw: [128][36] floats = 4608  (total 6912)
#define POOL_FLOATS 8448    // shf overlay: [64][132] floats = 8448 (33 KB)

__global__ __launch_bounds__(256) void k_gemm(const float* __restrict__ x,
                                              const float* __restrict__ W,
                                              const float* __restrict__ att_src,
                                              const float* __restrict__ att_dst) {
    __shared__ __align__(16) float s_pool[POOL_FLOATS];
    __shared__ float s_as[128], s_ad[128];
    float* sx  = s_pool + SX_OFF;
    float* sw  = s_pool + SW_OFF;
    float* shf = s_pool;                 // epilogue overlay [64][132]

    const int t      = threadIdx.x;
    const int wid    = t >> 5;
    const int n0     = blockIdx.x * 64;
    const int warp_m = wid & 3;          // 4 m-tiles of 16
    const int warp_n = wid >> 2;         // 2 n-tiles of 64

    if (t < 128) { s_as[t] = att_src[t]; s_ad[t] = att_dst[t]; }

    wmma::fragment<wmma::accumulator, 16, 16, 8, float> c[4];
#pragma unroll
    for (int nf = 0; nf < 4; nf++) wmma::fill_fragment(c[nf], 0.f);

    const float4* x4 = (const float4*)x;
    const float4* w4 = (const float4*)W;

#pragma unroll
    for (int kt = 0; kt < 4; kt++) {
        const int k0 = kt * 32;
        __syncthreads();
        // stage x tile: 64 rows x 32 floats; 4 threads/row, 8 floats each
        {
            const int r = t >> 2, cq = (t & 3) * 8;
            float4 v0 = make_float4(0.f, 0.f, 0.f, 0.f), v1 = v0;
            if (n0 + r < NN) {
                v0 = x4[(size_t)(n0 + r) * 32 + ((k0 + cq) >> 2)];
                v1 = x4[(size_t)(n0 + r) * 32 + ((k0 + cq) >> 2) + 1];
            }
            *(float4*)&sx[r * 36 + cq]     = v0;
            *(float4*)&sx[r * 36 + cq + 4] = v1;
        }
        // stage W tile: 128 rows x 32 floats; 2 threads/row, 16 floats each
        {
            const int r = t >> 1, cq = (t & 1) * 16;
#pragma unroll
            for (int q = 0; q < 4; q++)
                *(float4*)&sw[r * 36 + cq + 4 * q] =
                    w4[(size_t)r * 32 + ((k0 + cq) >> 2) + q];
        }
        __syncthreads();

#pragma unroll
        for (int k8 = 0; k8 < 4; k8++) {
            wmma::fragment<wmma::matrix_a, 16, 16, 8, wmma::precision::tf32,
                           wmma::row_major> a;
            wmma::load_matrix_sync(a, &sx[warp_m * 16 * 36 + k8 * 8], 36);
#pragma unroll
            for (int i = 0; i < a.num_elements; i++)
                a.x[i] = wmma::__float_to_tf32(a.x[i]);
#pragma unroll
            for (int nf = 0; nf < 4; nf++) {
                wmma::fragment<wmma::matrix_b, 16, 16, 8, wmma::precision::tf32,
                               wmma::col_major> b;
                wmma::load_matrix_sync(
                    b, &sw[(warp_n * 64 + nf * 16) * 36 + k8 * 8], 36);
#pragma unroll
                for (int i = 0; i < b.num_elements; i++)
                    b.x[i] = wmma::__float_to_tf32(b.x[i]);
                wmma::mma_sync(c[nf], a, b, c[nf]);
            }
        }
    }

    __syncthreads();   // A/B tiles dead; reuse pool as shf
#pragma unroll
    for (int nf = 0; nf < 4; nf++)
        wmma::store_matrix_sync(&shf[warp_m * 16 * 132 + warp_n * 64 + nf * 16],
                                c[nf], 132, wmma::mem_row_major);
    __syncthreads();

    // ---- epilogue A: thread = (node, head); 32-elem dot ----
    {
        const int nl = t >> 2, h = t & 3;
        const int m = n0 + nl;
        const float* base = &shf[nl * 132 + h * 32];
        float ps = 0.f, pd = 0.f;
#pragma unroll
        for (int d = 0; d < 32; d++) {
            ps += base[d] * s_as[h * 32 + d];
            pd += base[d] * s_ad[h * 32 + d];
        }
        if (m < NN) {
            ((float*)g_asrc)[m * 4 + h] = ps;
            ((float*)g_adst)[m * 4 + h] = pd;
        }
    }

    // ---- epilogue B: pack fp16 h, coalesced uint4 stores ----
    uint4* dstp = g_h16 + (size_t)n0 * 16;
#pragma unroll
    for (int r = 0; r < 4; r++) {
        const int idx = r * 256 + t;
        const int row = idx >> 4;
        if (n0 + row < NN) {
            const int c0 = (idx & 15) * 8;
            const float4 f0 = *(const float4*)&shf[row * 132 + c0];
            const float4 f1 = *(const float4*)&shf[row * 132 + c0 + 4];
            uint4 o;
            o.x = h2u(__floats2half2_rn(f0.x, f0.y));
            o.y = h2u(__floats2half2_rn(f0.z, f0.w));
            o.z = h2u(__floats2half2_rn(f1.x, f1.y));
            o.w = h2u(__floats2half2_rn(f1.z, f1.w));
            dstp[idx] = o;
        }
    }
}

// ---------------- K3a/b/c: 3-phase exclusive scan of degrees ----------------
__global__ __launch_bounds__(256) void k_scanA() {
    __shared__ int wsum[8];
    const int b = blockIdx.x, t = threadIdx.x, i = b * 256 + t;
    const int lane = t & 31, w = t >> 5;
    const int v = (i < NN) ? g_deg[i] : 0;
    int xs = v;
#pragma unroll
    for (int o = 1; o < 32; o <<= 1) {
        int y = __shfl_up_sync(0xffffffffu, xs, o);
        if (lane >= o) xs += y;
    }
    if (lane == 31) wsum[w] = xs;
    __syncthreads();
    if (t == 0) {
        int run = 0;
#pragma unroll
        for (int k = 0; k < 8; k++) { int tmp = wsum[k]; wsum[k] = run; run += tmp; }
        g_bsum[b] = run;
    }
    __syncthreads();
    if (i < NN) g_off[i] = wsum[w] + xs - v;
}

__global__ void k_scanB() {
    const int t = threadIdx.x;            // 32 threads
    int carry = 0;
    for (int c = 0; c < NB; c += 32) {
        const int idx = c + t;
        const int v = (idx < NB) ? g_bsum[idx] : 0;
        int xs = v;
#pragma unroll
        for (int o = 1; o < 32; o <<= 1) {
            int y = __shfl_up_sync(0xffffffffu, xs, o);
            if (t >= o) xs += y;
        }
        if (idx < NB) g_boff[idx] = carry + xs - v;
        carry += __shfl_sync(0xffffffffu, xs, 31);
    }
    if (t == 0) g_off[NN] = carry;
}

__global__ void k_scanC() {
    const int i = blockIdx.x * 256 + threadIdx.x;
    if (i < NN) {
        const int o = g_off[i] + g_boff[i >> 8];
        g_off[i] = o;
        g_cur[i] = o;
    }
}

// ---------------- K4: edge weights + direct CSR scatter ----------------
// smem-staged edge_attr for coalesced DRAM reads; max-free softmax (logits
// are O(1): max over 6.4M samples ~6, exp safe in fp32).
__global__ __launch_bounds__(256) void k_edge(const int* __restrict__ ei,
                                              const float* __restrict__ ea,
                                              const float* __restrict__ W_edge) {
    __shared__ float swe[64];
    __shared__ float sea[256][17];
    const int t = threadIdx.x;
    if (t < 64) swe[t] = W_edge[t];

    const int e0 = blockIdx.x * 256;        // NE % 256 == 0, no guards
    const float4* ea4 = (const float4*)ea + (size_t)e0 * 4;
#pragma unroll
    for (int r = 0; r < 4; r++) {
        const int idx = r * 256 + t;        // coalesced float4 index
        const float4 v = ea4[idx];
        const int er = idx >> 2, k = (idx & 3) * 4;
        sea[er][k] = v.x; sea[er][k+1] = v.y; sea[er][k+2] = v.z; sea[er][k+3] = v.w;
    }
    __syncthreads();

    const int e = e0 + t;
    const int s = ei[e];
    const int d = ei[NE + e];
    const float4 as = g_asrc[s];
    const float4 ad = g_adst[d];
    const float base[4] = {as.x + ad.x, as.y + ad.y, as.z + ad.z, as.w + ad.w};

    float lg[4];
#pragma unroll
    for (int h = 0; h < 4; h++) {
        const float* w = &swe[h * 16];
        float v = 0.f;
#pragma unroll
        for (int k = 0; k < 16; k++) v += sea[t][k] * w[k];
        v += base[h];
        v = (v > 0.f) ? v : 0.2f * v;       // leaky_relu(0.2)
        lg[h] = __expf(v);
    }
    const int pos = atomicAdd(&g_cur[d], 1);
    g_csr_src[pos] = s;
    g_csr_w[pos]   = make_float4(lg[0], lg[1], lg[2], lg[3]);
}

// ---------------- K5: dst-centric fused softmax + aggregation (fp16 h) ------
// warp per node; lane reads 8B (4 halves) of the 256B h row; head = lane>>3.
// h row for edge j+1 prefetched during edge j (one iteration of L2 cover).
__global__ __launch_bounds__(256) void k_agg(const float* __restrict__ bias,
                                             float* __restrict__ out) {
    const int wid  = threadIdx.x >> 5;
    const int lane = threadIdx.x & 31;
    const int n    = blockIdx.x * 8 + wid;
    if (n >= NN) return;

    const int beg = g_off[n];
    const int end = g_off[n + 1];
    const uint2* h2 = (const uint2*)g_h16;

    float a0 = 0.f, a1 = 0.f, a2 = 0.f, a3 = 0.f, dacc = 0.f;

    float4 wA = make_float4(0.f, 0.f, 0.f, 0.f);
    uint2  hA = make_uint2(0u, 0u);
    if (beg < end) {
        const int sA = g_csr_src[beg];
        wA = g_csr_w[beg];
        hA = h2[(size_t)sA * 32 + lane];
    }

    for (int j = beg; j < end; j++) {
        int sB = 0; float4 wB = wA;
        const bool more = (j + 1 < end);
        if (more) { sB = g_csr_src[j + 1]; wB = g_csr_w[j + 1]; }

        const float2 f01 = __half22float2(*(const __half2*)&hA.x);
        const float2 f23 = __half22float2(*(const __half2*)&hA.y);
        const float wsel = (lane & 16) ? ((lane & 8) ? wA.w : wA.z)
                                       : ((lane & 8) ? wA.y : wA.x);
        a0 += f01.x * wsel;
        a1 += f01.y * wsel;
        a2 += f23.x * wsel;
        a3 += f23.y * wsel;
        dacc += wsel;

        if (more) { hA = h2[(size_t)sB * 32 + lane]; wA = wB; }
    }

    const float inv = 1.f / (dacc + 1e-16f);
    float r0 = a0 * inv, r1 = a1 * inv, r2 = a2 * inv, r3 = a3 * inv;
#pragma unroll
    for (int off = 8; off <= 16; off <<= 1) {
        r0 += __shfl_xor_sync(0xffffffffu, r0, off);
        r1 += __shfl_xor_sync(0xffffffffu, r1, off);
        r2 += __shfl_xor_sync(0xffffffffu, r2, off);
        r3 += __shfl_xor_sync(0xffffffffu, r3, off);
    }
    if (lane < 8) {
        const float4 b4 = ((const float4*)bias)[lane];
        ((float4*)out)[n * 8 + lane] =
            make_float4(0.25f * r0 + b4.x, 0.25f * r1 + b4.y,
                        0.25f * r2 + b4.z, 0.25f * r3 + b4.w);
    }
}

// ---------------- launch ----------------
extern "C" void kernel_launch(void* const* d_in, const int* in_sizes, int n_in,
                              void* d_out, int out_size) {
    const float* x       = (const float*)d_in[0];
    const int*   ei      = (const int*)  d_in[1];
    const float* ea      = (const float*)d_in[2];
    const float* W_lin   = (const float*)d_in[3];
    const float* att_src = (const float*)d_in[4];
    const float* att_dst = (const float*)d_in[5];
    const float* bias    = (const float*)d_in[6];
    const float* W_edge  = (const float*)d_in[7];
    float* out = (float*)d_out;

    k_zero <<<NB, 256>>>();
    k_deg  <<<(NE + 255) / 256, 256>>>(ei);
    k_gemm <<<(NN + 63) / 64,   256>>>(x, W_lin, att_src, att_dst);
    k_scanA<<<NB, 256>>>();
    k_scanB<<<1, 32>>>();
    k_scanC<<<NB, 256>>>();
    k_edge <<<NE / 256, 256>>>(ei, ea, W_edge);
    k_agg  <<<(NN + 7) / 8, 256>>>(bias, out);
}